// round 2
// baseline (speedup 1.0000x reference)
#include <cuda_runtime.h>
#include <cuda_fp16.h>
#include <cstdint>

// ============================================================================
// cosine_layer: out[b,o] = dot(x[b,:], w[:,o]) / (max(||x_b||,eps)*max(||w_o||,eps))
//   x: [4096,4096] f32, w: [4096,32768] f32, out: [4096,32768] f32
//
// sm_103 base target (no tcgen05 — virtual arch is compute_103). Strategy:
//   1) prep: x -> fp16 SW128-swizzled K-major stage images + row partial sumsq
//   2) prep: w -> fp16*2^12 transposed [N,K] swizzled images + col partial sumsq
//   3) norms reduced deterministically; 2^12 folded into invw
//   4) GEMM via mma.sync m16n8k16 (HMMA), CTA tile 128x256x64, 8 warps
//      (warp tile 64x64), 3-stage cp.async pipeline, fused norm epilogue.
// ============================================================================

namespace {
constexpr int M_DIM = 4096;
constexpr int N_DIM = 32768;
constexpr int K_DIM = 4096;

constexpr int BM = 128;
constexpr int BN = 256;
constexpr int BK = 64;
constexpr int KT = K_DIM / BK;    // 64
constexpr int MT = M_DIM / BM;    // 32
constexpr int NT = N_DIM / BN;    // 128

constexpr int A_IMG = BM * BK * 2;         // 16384 B
constexpr int B_IMG = BN * BK * 2;         // 32768 B
constexpr int STAGE_B = A_IMG + B_IMG;     // 49152 B
constexpr int STAGES = 3;
constexpr int SMEM_TOTAL = STAGES * STAGE_B;  // 147456 B

constexpr float WSCALE = 4096.0f;   // 2^12, cancels in cosine (folded into invw)
constexpr float EPSN = 1e-8f;
}  // namespace

// ---------------------------------------------------------------------------
// Device scratch (static device globals -- allocation-free)
// ---------------------------------------------------------------------------
__device__ __align__(1024) __half g_xh[(size_t)M_DIM * K_DIM];   // 32 MB
__device__ __align__(1024) __half g_wh[(size_t)N_DIM * K_DIM];   // 256 MB
__device__ float g_xpart[KT * M_DIM];
__device__ float g_wpart[KT * N_DIM];
__device__ float g_invx[M_DIM];
__device__ float g_invw[N_DIM];

// ---------------------------------------------------------------------------
// helpers
// ---------------------------------------------------------------------------
__device__ __forceinline__ uint32_t smem_u32(const void* p) {
    uint32_t a;
    asm("{ .reg .u64 t; cvta.to.shared.u64 t, %1; cvt.u32.u64 %0, t; }"
        : "=r"(a) : "l"(p));
    return a;
}

__device__ __forceinline__ uint32_t swz128(uint32_t off) {
    return off ^ ((off >> 3) & 0x70);
}

#define CP16(saddr, gptr)                                                     \
    asm volatile("cp.async.cg.shared.global [%0], [%1], 16;"                  \
                 :: "r"(saddr), "l"(gptr) : "memory")

#define CP_COMMIT() asm volatile("cp.async.commit_group;" ::: "memory")

#define LDSM4(d0, d1, d2, d3, addr)                                           \
    asm volatile("ldmatrix.sync.aligned.m8n8.x4.shared.b16 {%0,%1,%2,%3}, [%4];" \
                 : "=r"(d0), "=r"(d1), "=r"(d2), "=r"(d3) : "r"(addr))

__device__ __forceinline__ void mma16816(float* d, const uint32_t* a,
                                         const uint32_t* b) {
    asm volatile(
        "mma.sync.aligned.m16n8k16.row.col.f32.f16.f16.f32 "
        "{%0,%1,%2,%3}, {%4,%5,%6,%7}, {%8,%9}, {%0,%1,%2,%3};"
        : "+f"(d[0]), "+f"(d[1]), "+f"(d[2]), "+f"(d[3])
        : "r"(a[0]), "r"(a[1]), "r"(a[2]), "r"(a[3]), "r"(b[0]), "r"(b[1]));
}

// ---------------------------------------------------------------------------
// Prep: x -> fp16 swizzled images + row partial sumsq. grid (MT,KT), 128 thr.
// ---------------------------------------------------------------------------
__global__ void cos_conv_x(const float* __restrict__ x) {
    const int mt = blockIdx.x, kt = blockIdx.y, t = threadIdx.x;
    const int m = mt * BM + t;
    const float4* src =
        reinterpret_cast<const float4*>(x + (size_t)m * K_DIM + kt * BK);
    float s = 0.0f;
    uint32_t h[32];
#pragma unroll
    for (int i = 0; i < 16; i++) {
        float4 v = src[i];
        s += v.x * v.x + v.y * v.y + v.z * v.z + v.w * v.w;
        __half2 p0 = __floats2half2_rn(v.x, v.y);
        __half2 p1 = __floats2half2_rn(v.z, v.w);
        h[2 * i]     = *reinterpret_cast<uint32_t*>(&p0);
        h[2 * i + 1] = *reinterpret_cast<uint32_t*>(&p1);
    }
    char* img = reinterpret_cast<char*>(g_xh) + (size_t)(mt * KT + kt) * A_IMG;
    const uint4* hv = reinterpret_cast<const uint4*>(h);
#pragma unroll
    for (int j = 0; j < 8; j++) {
        uint32_t off = swz128((uint32_t)(t * 128 + j * 16));
        *reinterpret_cast<uint4*>(img + off) = hv[j];
    }
    g_xpart[kt * M_DIM + m] = s;
}

// ---------------------------------------------------------------------------
// Prep: w -> fp16*2^12 transposed [N,K] images + col partial sumsq.
// grid (NT,KT), 256 thr.
// ---------------------------------------------------------------------------
__global__ void cos_conv_w(const float* __restrict__ w) {
    const int nt = blockIdx.x, kt = blockIdx.y, t = threadIdx.x;
    const int n = nt * BN + t;
    const float* base = w + (size_t)(kt * BK) * N_DIM + n;
    float s = 0.0f;
    uint32_t h[32];
#pragma unroll
    for (int j = 0; j < 32; j++) {
        float a = base[(size_t)(2 * j) * N_DIM];
        float b = base[(size_t)(2 * j + 1) * N_DIM];
        s += a * a + b * b;
        __half2 p = __floats2half2_rn(a * WSCALE, b * WSCALE);
        h[j] = *reinterpret_cast<uint32_t*>(&p);
    }
    char* img = reinterpret_cast<char*>(g_wh) + (size_t)(nt * KT + kt) * B_IMG;
    const uint4* hv = reinterpret_cast<const uint4*>(h);
#pragma unroll
    for (int j = 0; j < 8; j++) {
        uint32_t off = swz128((uint32_t)(t * 128 + j * 16));
        *reinterpret_cast<uint4*>(img + off) = hv[j];
    }
    g_wpart[kt * N_DIM + n] = s;
}

__global__ void cos_norm_x() {
    const int m = blockIdx.x * blockDim.x + threadIdx.x;
    float s = 0.0f;
#pragma unroll 8
    for (int kt = 0; kt < KT; kt++) s += g_xpart[kt * M_DIM + m];
    g_invx[m] = 1.0f / fmaxf(sqrtf(s), EPSN);
}

__global__ void cos_norm_w() {
    const int n = blockIdx.x * blockDim.x + threadIdx.x;
    float s = 0.0f;
#pragma unroll 8
    for (int kt = 0; kt < KT; kt++) s += g_wpart[kt * N_DIM + n];
    g_invw[n] = 1.0f / (fmaxf(sqrtf(s), EPSN) * WSCALE);
}

// ---------------------------------------------------------------------------
// GEMM: mma.sync m16n8k16, CTA 128x256x64, 8 warps (warp 64x64), 3-stage
// cp.async pipeline. grid (MT, NT) with mt fast for L2 reuse of B.
// ---------------------------------------------------------------------------
__device__ __forceinline__ void load_stage(uint32_t sbase, int slot,
                                           const char* gA, const char* gB,
                                           int t) {
    const uint32_t sA = sbase + slot * STAGE_B;
    const uint32_t sB = sA + A_IMG;
#pragma unroll
    for (int i = 0; i < 4; i++)
        CP16(sA + (uint32_t)(t + i * 256) * 16, gA + (size_t)(t + i * 256) * 16);
#pragma unroll
    for (int i = 0; i < 8; i++)
        CP16(sB + (uint32_t)(t + i * 256) * 16, gB + (size_t)(t + i * 256) * 16);
}

__global__ void __launch_bounds__(256, 1) cos_gemm(float* __restrict__ out) {
    extern __shared__ char smem[];
    const uint32_t sbase = smem_u32(smem);
    const int tid = threadIdx.x;
    const int wid = tid >> 5;
    const int lid = tid & 31;
    const int mt = blockIdx.x;
    const int nt = blockIdx.y;

    const int wm = wid & 1;   // m 64-block within CTA
    const int wn = wid >> 1;  // n 64-block within CTA

    // ldmatrix lane address precompute (SW128 swizzle linearized):
    // addr = row*128 + ((ks*32 | kg) ^ ((row&7)<<4))
    const int r = lid & 7, g = lid >> 3;
    const int rA = wm * 64 + (g & 1) * 8 + r;          // + i*16 per m-tile
    const uint32_t kgA = (uint32_t)(g >> 1) << 4;
    const uint32_t sxA = (uint32_t)(rA & 7) << 4;
    const int rB = wn * 64 + ((g >> 1) & 1) * 8 + r;   // + p*16 per n-pair
    const uint32_t kgB = (uint32_t)(g & 1) << 4;
    const uint32_t sxB = (uint32_t)(rB & 7) << 4;

    const char* gA = reinterpret_cast<const char*>(g_xh) + (size_t)(mt * KT) * A_IMG;
    const char* gB = reinterpret_cast<const char*>(g_wh) + (size_t)(nt * KT) * B_IMG;

    float acc[4][8][4];
#pragma unroll
    for (int i = 0; i < 4; i++)
#pragma unroll
        for (int j = 0; j < 8; j++)
#pragma unroll
            for (int c = 0; c < 4; c++) acc[i][j][c] = 0.0f;

    // prologue: stages 0 and 1
    load_stage(sbase, 0, gA, gB, tid);
    CP_COMMIT();
    load_stage(sbase, 1, gA + A_IMG, gB + B_IMG, tid);
    CP_COMMIT();

    int slot = 0;
    for (int it = 0; it < KT; ++it) {
        asm volatile("cp.async.wait_group 1;" ::: "memory");
        __syncthreads();

        const uint32_t stA = sbase + slot * STAGE_B;
        const uint32_t stB = stA + A_IMG;

#pragma unroll
        for (int ks = 0; ks < 4; ks++) {
            const uint32_t kb = (uint32_t)ks << 5;
            uint32_t a[4][4], b[8][2];
#pragma unroll
            for (int i = 0; i < 4; i++) {
                uint32_t ad = stA + (uint32_t)((rA + i * 16) * 128) + ((kb | kgA) ^ sxA);
                LDSM4(a[i][0], a[i][1], a[i][2], a[i][3], ad);
            }
#pragma unroll
            for (int p = 0; p < 4; p++) {
                uint32_t ad = stB + (uint32_t)((rB + p * 16) * 128) + ((kb | kgB) ^ sxB);
                LDSM4(b[2 * p][0], b[2 * p][1], b[2 * p + 1][0], b[2 * p + 1][1], ad);
            }
#pragma unroll
            for (int i = 0; i < 4; i++)
#pragma unroll
                for (int j = 0; j < 8; j++)
                    mma16816(acc[i][j], a[i], b[j]);
        }

        const int ktn = it + STAGES - 1;
        if (ktn < KT)
            load_stage(sbase, ktn % STAGES, gA + (size_t)ktn * A_IMG,
                       gB + (size_t)ktn * B_IMG, tid);
        CP_COMMIT();   // empty group when past the end keeps wait_group math valid

        if (++slot == STAGES) slot = 0;
    }

    // ---- epilogue: scale by norm reciprocals, write f32 ----
    const int qr = lid >> 2;
    const int qc = (lid & 3) * 2;
    const int mbase = mt * BM + wm * 64;
    const int nbase = nt * BN + wn * 64;
#pragma unroll
    for (int i = 0; i < 4; i++) {
        const int m0 = mbase + i * 16 + qr;
        const float ix0 = g_invx[m0];
        const float ix1 = g_invx[m0 + 8];
        float* row0 = out + (size_t)m0 * N_DIM + nbase;
        float* row1 = row0 + (size_t)8 * N_DIM;
#pragma unroll
        for (int j = 0; j < 8; j++) {
            const int nn = j * 8 + qc;
            const float iw0 = g_invw[nbase + nn];
            const float iw1 = g_invw[nbase + nn + 1];
            float2 v0, v1;
            v0.x = acc[i][j][0] * ix0 * iw0;
            v0.y = acc[i][j][1] * ix0 * iw1;
            v1.x = acc[i][j][2] * ix1 * iw0;
            v1.y = acc[i][j][3] * ix1 * iw1;
            *reinterpret_cast<float2*>(row0 + nn) = v0;
            *reinterpret_cast<float2*>(row1 + nn) = v1;
        }
    }
}

// ---------------------------------------------------------------------------
// kernel_launch
// ---------------------------------------------------------------------------
extern "C" void kernel_launch(void* const* d_in, const int* in_sizes, int n_in,
                              void* d_out, int out_size) {
    (void)in_sizes; (void)n_in; (void)out_size;
    const float* x = (const float*)d_in[0];
    const float* w = (const float*)d_in[1];
    float* out = (float*)d_out;

    cos_conv_x<<<dim3(MT, KT), BM>>>(x);
    cos_conv_w<<<dim3(NT, KT), BN>>>(w);
    cos_norm_x<<<M_DIM / 256, 256>>>();
    cos_norm_w<<<N_DIM / 256, 256>>>();

    cudaFuncSetAttribute(cos_gemm, cudaFuncAttributeMaxDynamicSharedMemorySize,
                         SMEM_TOTAL);
    cos_gemm<<<dim3(MT, NT), 256, SMEM_TOTAL>>>(out);
}